// round 9
// baseline (speedup 1.0000x reference)
#include <cuda_runtime.h>
#include <cuda_fp16.h>
#include <math.h>

#define BATCH   1024
#define N_IN    1024
#define NLAYERS 5
#define NPL     2048
#define FANIN   16
#define N_OUT   256
#define W_ROWS  (N_IN + 4 * NPL)   // 9216
#define ROW_BYTES (BATCH * 2)
#define L2_BASE (N_IN + 2 * NPL)   // 5120
#define L3_BASE (N_IN + 3 * NPL)   // 7168

// Transposed fp16 value buffer: valsT[row, batch]. 18.9 MB, L2-resident.
__device__ __half g_vals[(size_t)W_ROWS * BATCH];
// Liveness bitmaps for layers 2 and 3 (bit n = node n of that layer).
__device__ unsigned g_liveL2[NPL / 32];
__device__ unsigned g_liveL3[NPL / 32];

__device__ __forceinline__ float tanh_approx(float x) {
    float y;
    asm("tanh.approx.f32 %0, %1;" : "=f"(y) : "f"(x));
    return y;
}

// ---------------------------------------------------------------------------
// Transpose + liveness fused launch.
// Blocks 0..1023: transpose input [B,N_IN] f32 -> g_vals[N_IN,B] f16.
// Block 1024:     compute L2/L3 liveness bitmaps (hides under the transpose).
// ---------------------------------------------------------------------------
__global__ void __launch_bounds__(256) transpose_live_kernel(
    const float* __restrict__ in,
    const int*   __restrict__ src_l3,   // layer-3 edge_src [NPL, FANIN]
    const int*   __restrict__ src_l4)   // layer-4 edge_src [NPL, FANIN]
{
    if (blockIdx.x < 1024) {
        __shared__ float tile[32][33];
        const int tileid = blockIdx.x;
        const int bx = (tileid & 31) * 32;   // column tile
        const int by = (tileid >> 5) * 32;   // batch tile
        const int tx = threadIdx.x & 31;
        const int ty = threadIdx.x >> 5;     // 0..7
#pragma unroll
        for (int j = 0; j < 32; j += 8)
            tile[ty + j][tx] = in[(size_t)(by + ty + j) * N_IN + bx + tx];
        __syncthreads();
#pragma unroll
        for (int j = 0; j < 32; j += 8)
            g_vals[(size_t)(bx + ty + j) * BATCH + by + tx] =
                __float2half_rn(tile[tx][ty + j]);
        return;
    }

    // --- liveness block ---
    __shared__ unsigned bmL3[NPL / 32];
    __shared__ unsigned bmL2[NPL / 32];
    const int t = threadIdx.x;

    if (t < NPL / 32) { bmL3[t] = 0u; bmL2[t] = 0u; }
    __syncthreads();

    // Phase 1: sources of the final N_OUT output nodes (one node per thread).
    {
        const int4* s4 = (const int4*)(src_l4 + (NPL - N_OUT + t) * FANIN);
#pragma unroll
        for (int q = 0; q < FANIN / 4; q++) {
            int4 si = __ldg(s4 + q);
            int v[4] = { si.x, si.y, si.z, si.w };
#pragma unroll
            for (int k = 0; k < 4; k++) {
                int idx = v[k];
                if (idx >= L3_BASE) {
                    int n = idx - L3_BASE;
                    atomicOr(&bmL3[n >> 5], 1u << (n & 31));
                } else if (idx >= L2_BASE) {
                    int n = idx - L2_BASE;
                    atomicOr(&bmL2[n >> 5], 1u << (n & 31));
                }
            }
        }
    }
    __syncthreads();

    // Phase 2: live layer-3 nodes mark their layer-2 sources.
#pragma unroll 1
    for (int n = t; n < NPL; n += 256) {
        if ((bmL3[n >> 5] >> (n & 31)) & 1u) {
            const int4* s4 = (const int4*)(src_l3 + n * FANIN);
#pragma unroll
            for (int q = 0; q < FANIN / 4; q++) {
                int4 si = __ldg(s4 + q);
                int v[4] = { si.x, si.y, si.z, si.w };
#pragma unroll
                for (int k = 0; k < 4; k++) {
                    int idx = v[k];
                    if (idx >= L2_BASE) {   // layer-3 srcs are all < L3_BASE
                        int m = idx - L2_BASE;
                        atomicOr(&bmL2[m >> 5], 1u << (m & 31));
                    }
                }
            }
        }
    }
    __syncthreads();

    if (t < NPL / 32) { g_liveL3[t] = bmL3[t]; g_liveL2[t] = bmL2[t]; }
}

// ---------------------------------------------------------------------------
// Hidden layer. Block = 2 nodes x 128 threads; 8 batch elems/thread.
// Gathers issued in GROUPS OF 4 (anti front-batching: keeps the per-warp
// L1tex queue footprint small to cut cross-CTA spread).
// mode: 0 = no pruning, 2 = test g_liveL2, 3 = test g_liveL3.
// ---------------------------------------------------------------------------
__global__ void __launch_bounds__(256) layer_kernel(
    const int*   __restrict__ src,
    const float* __restrict__ wgt,
    const float* __restrict__ bias,
    int out_base_row, int mode)
{
    const int n = blockIdx.x * 2 + (threadIdx.x >> 7);
    const int t = threadIdx.x & 127;

    if (mode != 0) {
        const unsigned* lm = (mode == 3) ? g_liveL3 : g_liveL2;
        if (!((lm[n >> 5] >> (n & 31)) & 1u)) return;   // dead node
    }

    float bv = __ldg(bias + n);
    float acc[8];
#pragma unroll
    for (int i = 0; i < 8; i++) acc[i] = bv;

    const char* gbase = (const char*)g_vals;
    const unsigned toff = (unsigned)t * 16u;
    const int4*   s4 = (const int4*)(src + n * FANIN);
    const float4* w4 = (const float4*)(wgt + n * FANIN);

#pragma unroll 1
    for (int q = 0; q < FANIN / 4; q++) {
        int4   si = __ldg(s4 + q);
        float4 wi = __ldg(w4 + q);
        // 4 gathers in flight, then consume.
        uint4 v0 = *(const uint4*)(gbase + (unsigned)si.x * (unsigned)ROW_BYTES + toff);
        uint4 v1 = *(const uint4*)(gbase + (unsigned)si.y * (unsigned)ROW_BYTES + toff);
        uint4 v2 = *(const uint4*)(gbase + (unsigned)si.z * (unsigned)ROW_BYTES + toff);
        uint4 v3 = *(const uint4*)(gbase + (unsigned)si.w * (unsigned)ROW_BYTES + toff);

        const uint4* vv[4] = { &v0, &v1, &v2, &v3 };
        float ww[4] = { wi.x, wi.y, wi.z, wi.w };
#pragma unroll
        for (int k = 0; k < 4; k++) {
            uint4 v = *vv[k];
            float wf = ww[k];
            float2 f0 = __half22float2(*(__half2*)&v.x);
            float2 f1 = __half22float2(*(__half2*)&v.y);
            float2 f2 = __half22float2(*(__half2*)&v.z);
            float2 f3 = __half22float2(*(__half2*)&v.w);
            acc[0] = fmaf(wf, f0.x, acc[0]);
            acc[1] = fmaf(wf, f0.y, acc[1]);
            acc[2] = fmaf(wf, f1.x, acc[2]);
            acc[3] = fmaf(wf, f1.y, acc[3]);
            acc[4] = fmaf(wf, f2.x, acc[4]);
            acc[5] = fmaf(wf, f2.y, acc[5]);
            acc[6] = fmaf(wf, f3.x, acc[6]);
            acc[7] = fmaf(wf, f3.y, acc[7]);
        }
    }

#pragma unroll
    for (int i = 0; i < 8; i++) acc[i] = tanh_approx(acc[i]);

    uint4 o;
    *(__half2*)&o.x = __floats2half2_rn(acc[0], acc[1]);
    *(__half2*)&o.y = __floats2half2_rn(acc[2], acc[3]);
    *(__half2*)&o.z = __floats2half2_rn(acc[4], acc[5]);
    *(__half2*)&o.w = __floats2half2_rn(acc[6], acc[7]);
    *(uint4*)&g_vals[(size_t)(out_base_row + n) * BATCH + t * 8] = o;
}

// ---------------------------------------------------------------------------
// Final layer: last N_OUT nodes, sigmoid, f32 out [B, N_OUT].
// ---------------------------------------------------------------------------
__global__ void __launch_bounds__(256) final_layer_kernel(
    const int*   __restrict__ src,
    const float* __restrict__ wgt,
    const float* __restrict__ bias,
    float*       __restrict__ out)
{
    const int j = blockIdx.x * 2 + (threadIdx.x >> 7);
    const int n = NPL - N_OUT + j;
    const int t = threadIdx.x & 127;

    float bv = __ldg(bias + n);
    float acc[8];
#pragma unroll
    for (int i = 0; i < 8; i++) acc[i] = bv;

    const char* gbase = (const char*)g_vals;
    const unsigned toff = (unsigned)t * 16u;
    const int4*   s4 = (const int4*)(src + n * FANIN);
    const float4* w4 = (const float4*)(wgt + n * FANIN);

#pragma unroll 1
    for (int q = 0; q < FANIN / 4; q++) {
        int4   si = __ldg(s4 + q);
        float4 wi = __ldg(w4 + q);
        uint4 v0 = *(const uint4*)(gbase + (unsigned)si.x * (unsigned)ROW_BYTES + toff);
        uint4 v1 = *(const uint4*)(gbase + (unsigned)si.y * (unsigned)ROW_BYTES + toff);
        uint4 v2 = *(const uint4*)(gbase + (unsigned)si.z * (unsigned)ROW_BYTES + toff);
        uint4 v3 = *(const uint4*)(gbase + (unsigned)si.w * (unsigned)ROW_BYTES + toff);

        const uint4* vv[4] = { &v0, &v1, &v2, &v3 };
        float ww[4] = { wi.x, wi.y, wi.z, wi.w };
#pragma unroll
        for (int k = 0; k < 4; k++) {
            uint4 v = *vv[k];
            float wf = ww[k];
            float2 f0 = __half22float2(*(__half2*)&v.x);
            float2 f1 = __half22float2(*(__half2*)&v.y);
            float2 f2 = __half22float2(*(__half2*)&v.z);
            float2 f3 = __half22float2(*(__half2*)&v.w);
            acc[0] = fmaf(wf, f0.x, acc[0]);
            acc[1] = fmaf(wf, f0.y, acc[1]);
            acc[2] = fmaf(wf, f1.x, acc[2]);
            acc[3] = fmaf(wf, f1.y, acc[3]);
            acc[4] = fmaf(wf, f2.x, acc[4]);
            acc[5] = fmaf(wf, f2.y, acc[5]);
            acc[6] = fmaf(wf, f3.x, acc[6]);
            acc[7] = fmaf(wf, f3.y, acc[7]);
        }
    }

    const int b = t * 8;
#pragma unroll
    for (int i = 0; i < 8; i++) {
        float s = 1.0f / (1.0f + expf(-acc[i]));
        out[(size_t)(b + i) * N_OUT + j] = s;
    }
}

// ---------------------------------------------------------------------------
extern "C" void kernel_launch(void* const* d_in, const int* in_sizes, int n_in,
                              void* d_out, int out_size) {
    const float* inputs   = (const float*)d_in[0];   // [B, N_IN]
    const int*   edge_src = (const int*)  d_in[1];   // [L, NPL, FANIN]
    const float* edge_w   = (const float*)d_in[2];   // [L, NPL, FANIN]
    const float* biases   = (const float*)d_in[3];   // [L, NPL]
    float*       out      = (float*)d_out;

    // Transpose (blocks 0..1023) + liveness (block 1024) in one launch.
    transpose_live_kernel<<<1025, 256>>>(
        inputs,
        edge_src + (size_t)3 * NPL * FANIN,
        edge_src + (size_t)4 * NPL * FANIN);

    for (int l = 0; l < NLAYERS - 1; l++) {
        int mode = (l == 2) ? 2 : (l == 3) ? 3 : 0;
        layer_kernel<<<NPL / 2, 256>>>(
            edge_src + (size_t)l * NPL * FANIN,
            edge_w   + (size_t)l * NPL * FANIN,
            biases   + (size_t)l * NPL,
            N_IN + l * NPL, mode);
    }

    final_layer_kernel<<<N_OUT / 2, 256>>>(
        edge_src + (size_t)4 * NPL * FANIN,
        edge_w   + (size_t)4 * NPL * FANIN,
        biases   + (size_t)4 * NPL,
        out);
}

// round 10
// speedup vs baseline: 1.0584x; 1.0584x over previous
#include <cuda_runtime.h>
#include <cuda_device_runtime_api.h>
#include <cuda_fp16.h>
#include <math.h>

#define BATCH   1024
#define N_IN    1024
#define NLAYERS 5
#define NPL     2048
#define FANIN   16
#define N_OUT   256
#define W_ROWS  (N_IN + 4 * NPL)   // 9216
#define ROW_BYTES (BATCH * 2)
#define L2_BASE (N_IN + 2 * NPL)   // 5120
#define L3_BASE (N_IN + 3 * NPL)   // 7168

// Transposed fp16 value buffer: valsT[row, batch]. 18.9 MB, L2-resident.
__device__ __half g_vals[(size_t)W_ROWS * BATCH];
// Liveness bitmaps for layers 2 and 3 (bit n = node n of that layer).
__device__ unsigned g_liveL2[NPL / 32];
__device__ unsigned g_liveL3[NPL / 32];

__device__ __forceinline__ float tanh_approx(float x) {
    float y;
    asm("tanh.approx.f32 %0, %1;" : "=f"(y) : "f"(x));
    return y;
}

// ---------------------------------------------------------------------------
// Transpose + liveness fused launch (first kernel; no PDL wait needed).
// Blocks 0..1023: transpose input [B,N_IN] f32 -> g_vals[N_IN,B] f16.
// Block 1024:     L2/L3 liveness bitmaps (hides under the transpose).
// ---------------------------------------------------------------------------
__global__ void __launch_bounds__(256) transpose_live_kernel(
    const float* __restrict__ in,
    const int*   __restrict__ src_l3,
    const int*   __restrict__ src_l4)
{
    if (blockIdx.x < 1024) {
        __shared__ float tile[32][33];
        const int tileid = blockIdx.x;
        const int bx = (tileid & 31) * 32;
        const int by = (tileid >> 5) * 32;
        const int tx = threadIdx.x & 31;
        const int ty = threadIdx.x >> 5;
#pragma unroll
        for (int j = 0; j < 32; j += 8)
            tile[ty + j][tx] = in[(size_t)(by + ty + j) * N_IN + bx + tx];
        __syncthreads();
#pragma unroll
        for (int j = 0; j < 32; j += 8)
            g_vals[(size_t)(bx + ty + j) * BATCH + by + tx] =
                __float2half_rn(tile[tx][ty + j]);
        cudaTriggerProgrammaticLaunchCompletion();
        return;
    }

    // --- liveness block ---
    __shared__ unsigned bmL3[NPL / 32];
    __shared__ unsigned bmL2[NPL / 32];
    const int t = threadIdx.x;

    if (t < NPL / 32) { bmL3[t] = 0u; bmL2[t] = 0u; }
    __syncthreads();

    {   // Phase 1: sources of the final N_OUT output nodes.
        const int4* s4 = (const int4*)(src_l4 + (NPL - N_OUT + t) * FANIN);
#pragma unroll
        for (int q = 0; q < FANIN / 4; q++) {
            int4 si = __ldg(s4 + q);
            int v[4] = { si.x, si.y, si.z, si.w };
#pragma unroll
            for (int k = 0; k < 4; k++) {
                int idx = v[k];
                if (idx >= L3_BASE) {
                    int n = idx - L3_BASE;
                    atomicOr(&bmL3[n >> 5], 1u << (n & 31));
                } else if (idx >= L2_BASE) {
                    int n = idx - L2_BASE;
                    atomicOr(&bmL2[n >> 5], 1u << (n & 31));
                }
            }
        }
    }
    __syncthreads();

    // Phase 2: live layer-3 nodes mark their layer-2 sources.
#pragma unroll 1
    for (int n = t; n < NPL; n += 256) {
        if ((bmL3[n >> 5] >> (n & 31)) & 1u) {
            const int4* s4 = (const int4*)(src_l3 + n * FANIN);
#pragma unroll
            for (int q = 0; q < FANIN / 4; q++) {
                int4 si = __ldg(s4 + q);
                int v[4] = { si.x, si.y, si.z, si.w };
#pragma unroll
                for (int k = 0; k < 4; k++) {
                    int idx = v[k];
                    if (idx >= L2_BASE) {
                        int m = idx - L2_BASE;
                        atomicOr(&bmL2[m >> 5], 1u << (m & 31));
                    }
                }
            }
        }
    }
    __syncthreads();

    if (t < NPL / 32) { g_liveL3[t] = bmL3[t]; g_liveL2[t] = bmL2[t]; }
}

// ---------------------------------------------------------------------------
// Hidden layer (PDL). Prologue (idx/weights/bias) loads BEFORE the grid
// dependency sync -> overlaps the previous kernel's tail. Gathers after sync.
// Block = 2 nodes x 128 threads; 8 batch elems/thread, 16 batched LDG.128.
// mode: 0 = no pruning, 2 = g_liveL2, 3 = g_liveL3.
// ---------------------------------------------------------------------------
__global__ void __launch_bounds__(256) layer_kernel(
    const int*   __restrict__ src,
    const float* __restrict__ wgt,
    const float* __restrict__ bias,
    int out_base_row, int mode)
{
    const int n = blockIdx.x * 2 + (threadIdx.x >> 7);
    const int t = threadIdx.x & 127;

    // ---- prologue: independent of predecessor ----
    int   sidx[FANIN];
    float wv[FANIN];
    {
        const int4*   s4 = (const int4*)(src + n * FANIN);
        const float4* w4 = (const float4*)(wgt + n * FANIN);
#pragma unroll
        for (int q = 0; q < FANIN / 4; q++) {
            int4   si = __ldg(s4 + q);
            float4 wi = __ldg(w4 + q);
            sidx[q*4+0] = si.x; sidx[q*4+1] = si.y;
            sidx[q*4+2] = si.z; sidx[q*4+3] = si.w;
            wv[q*4+0] = wi.x; wv[q*4+1] = wi.y;
            wv[q*4+2] = wi.z; wv[q*4+3] = wi.w;
        }
    }
    float bv = __ldg(bias + n);

    // ---- wait for predecessor's g_vals writes (and liveness bitmaps) ----
    cudaGridDependencySynchronize();

    if (mode != 0) {
        const unsigned* lm = (mode == 3) ? g_liveL3 : g_liveL2;
        if (!((lm[n >> 5] >> (n & 31)) & 1u)) return;   // dead node
    }

    float acc[8];
#pragma unroll
    for (int i = 0; i < 8; i++) acc[i] = bv;

    const char* gbase = (const char*)g_vals;
    const unsigned toff = (unsigned)t * 16u;
#pragma unroll
    for (int f = 0; f < FANIN; f++) {
        uint4 v = *(const uint4*)(gbase + (unsigned)sidx[f] * (unsigned)ROW_BYTES + toff);
        float wf = wv[f];
        float2 f0 = __half22float2(*(__half2*)&v.x);
        float2 f1 = __half22float2(*(__half2*)&v.y);
        float2 f2 = __half22float2(*(__half2*)&v.z);
        float2 f3 = __half22float2(*(__half2*)&v.w);
        acc[0] = fmaf(wf, f0.x, acc[0]);
        acc[1] = fmaf(wf, f0.y, acc[1]);
        acc[2] = fmaf(wf, f1.x, acc[2]);
        acc[3] = fmaf(wf, f1.y, acc[3]);
        acc[4] = fmaf(wf, f2.x, acc[4]);
        acc[5] = fmaf(wf, f2.y, acc[5]);
        acc[6] = fmaf(wf, f3.x, acc[6]);
        acc[7] = fmaf(wf, f3.y, acc[7]);
    }

#pragma unroll
    for (int i = 0; i < 8; i++) acc[i] = tanh_approx(acc[i]);

    uint4 o;
    *(__half2*)&o.x = __floats2half2_rn(acc[0], acc[1]);
    *(__half2*)&o.y = __floats2half2_rn(acc[2], acc[3]);
    *(__half2*)&o.z = __floats2half2_rn(acc[4], acc[5]);
    *(__half2*)&o.w = __floats2half2_rn(acc[6], acc[7]);
    *(uint4*)&g_vals[(size_t)(out_base_row + n) * BATCH + t * 8] = o;
    cudaTriggerProgrammaticLaunchCompletion();
}

// ---------------------------------------------------------------------------
// Final layer (PDL): last N_OUT nodes, sigmoid, f32 out [B, N_OUT].
// ---------------------------------------------------------------------------
__global__ void __launch_bounds__(256) final_layer_kernel(
    const int*   __restrict__ src,
    const float* __restrict__ wgt,
    const float* __restrict__ bias,
    float*       __restrict__ out)
{
    const int j = blockIdx.x * 2 + (threadIdx.x >> 7);
    const int n = NPL - N_OUT + j;
    const int t = threadIdx.x & 127;

    int   sidx[FANIN];
    float wv[FANIN];
    {
        const int4*   s4 = (const int4*)(src + n * FANIN);
        const float4* w4 = (const float4*)(wgt + n * FANIN);
#pragma unroll
        for (int q = 0; q < FANIN / 4; q++) {
            int4   si = __ldg(s4 + q);
            float4 wi = __ldg(w4 + q);
            sidx[q*4+0] = si.x; sidx[q*4+1] = si.y;
            sidx[q*4+2] = si.z; sidx[q*4+3] = si.w;
            wv[q*4+0] = wi.x; wv[q*4+1] = wi.y;
            wv[q*4+2] = wi.z; wv[q*4+3] = wi.w;
        }
    }
    float bv = __ldg(bias + n);

    cudaGridDependencySynchronize();

    float acc[8];
#pragma unroll
    for (int i = 0; i < 8; i++) acc[i] = bv;

    const char* gbase = (const char*)g_vals;
    const unsigned toff = (unsigned)t * 16u;
#pragma unroll
    for (int f = 0; f < FANIN; f++) {
        uint4 v = *(const uint4*)(gbase + (unsigned)sidx[f] * (unsigned)ROW_BYTES + toff);
        float wf = wv[f];
        float2 f0 = __half22float2(*(__half2*)&v.x);
        float2 f1 = __half22float2(*(__half2*)&v.y);
        float2 f2 = __half22float2(*(__half2*)&v.z);
        float2 f3 = __half22float2(*(__half2*)&v.w);
        acc[0] = fmaf(wf, f0.x, acc[0]);
        acc[1] = fmaf(wf, f0.y, acc[1]);
        acc[2] = fmaf(wf, f1.x, acc[2]);
        acc[3] = fmaf(wf, f1.y, acc[3]);
        acc[4] = fmaf(wf, f2.x, acc[4]);
        acc[5] = fmaf(wf, f2.y, acc[5]);
        acc[6] = fmaf(wf, f3.x, acc[6]);
        acc[7] = fmaf(wf, f3.y, acc[7]);
    }

    const int b = t * 8;
#pragma unroll
    for (int i = 0; i < 8; i++) {
        float s = 1.0f / (1.0f + expf(-acc[i]));
        out[(size_t)(b + i) * N_OUT + j] = s;
    }
}

// ---------------------------------------------------------------------------
static inline void launch_pdl(void* fn, dim3 grid, dim3 block, void** args) {
    cudaLaunchConfig_t cfg = {};
    cfg.gridDim = grid;
    cfg.blockDim = block;
    cfg.stream = 0;
    cudaLaunchAttribute attr[1];
    attr[0].id = cudaLaunchAttributeProgrammaticStreamSerialization;
    attr[0].val.programmaticStreamSerializationAllowed = 1;
    cfg.attrs = attr;
    cfg.numAttrs = 1;
    cudaLaunchKernelExC(&cfg, fn, args);
}

extern "C" void kernel_launch(void* const* d_in, const int* in_sizes, int n_in,
                              void* d_out, int out_size) {
    const float* inputs   = (const float*)d_in[0];   // [B, N_IN]
    const int*   edge_src = (const int*)  d_in[1];   // [L, NPL, FANIN]
    const float* edge_w   = (const float*)d_in[2];   // [L, NPL, FANIN]
    const float* biases   = (const float*)d_in[3];   // [L, NPL]
    float*       out      = (float*)d_out;

    // Kernel 0: transpose + liveness (plain launch).
    transpose_live_kernel<<<1025, 256>>>(
        inputs,
        edge_src + (size_t)3 * NPL * FANIN,
        edge_src + (size_t)4 * NPL * FANIN);

    // Kernels 1..4: hidden layers with PDL overlap.
    for (int l = 0; l < NLAYERS - 1; l++) {
        int mode = (l == 2) ? 2 : (l == 3) ? 3 : 0;
        const int*   src = edge_src + (size_t)l * NPL * FANIN;
        const float* wgt = edge_w   + (size_t)l * NPL * FANIN;
        const float* bia = biases   + (size_t)l * NPL;
        int base = N_IN + l * NPL;
        void* args[] = { (void*)&src, (void*)&wgt, (void*)&bia,
                         (void*)&base, (void*)&mode };
        launch_pdl((void*)layer_kernel, dim3(NPL / 2), dim3(256), args);
    }

    // Kernel 5: final layer with PDL overlap.
    {
        const int*   src = edge_src + (size_t)4 * NPL * FANIN;
        const float* wgt = edge_w   + (size_t)4 * NPL * FANIN;
        const float* bia = biases   + (size_t)4 * NPL;
        void* args[] = { (void*)&src, (void*)&wgt, (void*)&bia, (void*)&out };
        launch_pdl((void*)final_layer_kernel, dim3(N_OUT / 2), dim3(256), args);
    }
}